// round 5
// baseline (speedup 1.0000x reference)
#include <cuda_runtime.h>
#include <math.h>

// Problem constants (fixed by the reference)
constexpr int HID   = 896;    // hidden
constexpr int INTR  = 2560;   // intermediate
constexpr int NEXP  = 16;     // experts
constexpr int TOPK  = 4;
constexpr int MAXT  = 2048;   // tokens (2*1024)
constexpr int ROWS_ROUTED = MAXT * TOPK;           // 8192 (exact)
constexpr int ROWS_TOTAL  = ROWS_ROUTED + MAXT;    // + shared expert rows

// ---------------- scratch (static __device__ -> allowed) ----------------
__device__ int   g_count[NEXP];
__device__ int   g_off[NEXP];          // exclusive prefix of counts
__device__ float g_probsum[NEXP];
__device__ int   g_tok[NEXP * MAXT];
__device__ float g_wt [NEXP * MAXT];
// compacted h activations: routed rows [0, 8192) grouped by expert, shared rows [8192, 10240)
__device__ float g_h[(size_t)ROWS_TOTAL * INTR];   // ~100 MB

// ---------------- kernel 1: zero outputs + counters ----------------
__global__ void zero_kernel(float* __restrict__ out, int n) {
    int i = blockIdx.x * blockDim.x + threadIdx.x;
    if (i < n) out[i] = 0.0f;
    if (blockIdx.x == 0 && threadIdx.x < NEXP) {
        g_count[threadIdx.x]   = 0;
        g_probsum[threadIdx.x] = 0.0f;
    }
}

// ---------------- kernel 2: router (1 warp per token) ----------------
__global__ void router_kernel(const float* __restrict__ x,
                              const float* __restrict__ rw, int T) {
    int warp = (blockIdx.x * blockDim.x + threadIdx.x) >> 5;
    int lane = threadIdx.x & 31;
    if (warp >= T) return;
    const float* xr = x + (size_t)warp * HID;

    // lanes 0..15 each own one expert's logit
    float logit = -1e30f;
    if (lane < NEXP) {
        float s = 0.0f;
        for (int d = 0; d < HID; d++) s += xr[d] * rw[d * NEXP + lane];
        logit = s;
    }
    // softmax over lanes 0..15 (xor-group {8,4,2,1} is closed within [0,16))
    float m = logit;
    #pragma unroll
    for (int o = 8; o >= 1; o >>= 1) m = fmaxf(m, __shfl_xor_sync(0xffffffffu, m, o));
    float p = (lane < NEXP) ? __expf(logit - m) : 0.0f;
    float sum = p;
    #pragma unroll
    for (int o = 8; o >= 1; o >>= 1) sum += __shfl_xor_sync(0xffffffffu, sum, o);
    p = p / sum;

    if (lane < NEXP) atomicAdd(&g_probsum[lane], p);

    // gather all 16 probs to every lane, lane 0 does top-4
    float pv[NEXP];
    #pragma unroll
    for (int e = 0; e < NEXP; e++) pv[e] = __shfl_sync(0xffffffffu, p, e);

    if (lane == 0) {
        bool used[NEXP];
        #pragma unroll
        for (int e = 0; e < NEXP; e++) used[e] = false;
        int   idx[TOPK];
        float val[TOPK];
        float s4 = 0.0f;
        #pragma unroll
        for (int k = 0; k < TOPK; k++) {
            int bi = -1; float bv = -1.0f;
            #pragma unroll
            for (int e = 0; e < NEXP; e++)
                if (!used[e] && pv[e] > bv) { bv = pv[e]; bi = e; }
            used[bi] = true; idx[k] = bi; val[k] = bv; s4 += bv;
        }
        float inv = 1.0f / (s4 + 1e-8f);
        #pragma unroll
        for (int k = 0; k < TOPK; k++) {
            int e = idx[k];
            int pos = atomicAdd(&g_count[e], 1);
            g_tok[e * MAXT + pos] = warp;
            g_wt [e * MAXT + pos] = val[k] * inv;
        }
    }
}

// ---------------- kernel 3: prefix offsets + balance loss ----------------
__global__ void finalize_kernel(float* __restrict__ out, int T, int ofs, int has_loss) {
    if (threadIdx.x == 0) {
        int s = 0;
        float loss = 0.0f;
        for (int e = 0; e < NEXP; e++) {
            g_off[e] = s;
            s += g_count[e];
            loss += ((float)g_count[e] / (float)T) * (g_probsum[e] / (float)T);
        }
        if (has_loss) out[ofs] = loss * (float)NEXP;
    }
}

// ---------------- kernel 4: GEMM1  h = silu(x*Wg) * (x*Wu) ----------------
// grid: (INTR/64, ceil(T/64), 17), block 256 (16x16), tile 64x64, BK=16
__global__ void gemm1_kernel(const float* __restrict__ x,
                             const float* __restrict__ Wg, const float* __restrict__ Wu,
                             const float* __restrict__ Sg, const float* __restrict__ Su,
                             int T) {
    int slot  = blockIdx.z;
    int rows  = (slot < NEXP) ? g_count[slot] : T;
    int mbase = blockIdx.y * 64;
    if (mbase >= rows) return;
    int n0 = blockIdx.x * 64;
    int rowbase = (slot < NEXP) ? g_off[slot] : ROWS_ROUTED;  // compacted h row base

    const float* Bg = (slot < NEXP) ? Wg + (size_t)slot * HID * INTR : Sg;
    const float* Bu = (slot < NEXP) ? Wu + (size_t)slot * HID * INTR : Su;

    __shared__ float Xs [16][64];
    __shared__ float Bgs[16][64];
    __shared__ float Bus[16][64];

    int tid = threadIdx.x;
    int tx = tid & 15, ty = tid >> 4;

    // A loader mapping: 4 threads per row, float4 each
    int lm = tid >> 2, lq = tid & 3;
    bool avalid = (mbase + lm) < rows;
    size_t xoff = 0;
    if (avalid) {
        int tok = (slot < NEXP) ? g_tok[slot * MAXT + mbase + lm] : (mbase + lm);
        xoff = (size_t)tok * HID;
    }
    // B loader mapping: 16 threads per row, float4 each
    int bk = tid >> 4, bn = tid & 15;

    float accg[4][4] = {}, accu[4][4] = {};

    for (int k0 = 0; k0 < HID; k0 += 16) {
        float4 av = make_float4(0.f, 0.f, 0.f, 0.f);
        if (avalid) av = *(const float4*)(x + xoff + k0 + lq * 4);
        Xs[lq * 4 + 0][lm] = av.x;
        Xs[lq * 4 + 1][lm] = av.y;
        Xs[lq * 4 + 2][lm] = av.z;
        Xs[lq * 4 + 3][lm] = av.w;
        *(float4*)&Bgs[bk][bn * 4] = *(const float4*)(Bg + (size_t)(k0 + bk) * INTR + n0 + bn * 4);
        *(float4*)&Bus[bk][bn * 4] = *(const float4*)(Bu + (size_t)(k0 + bk) * INTR + n0 + bn * 4);
        __syncthreads();
        #pragma unroll
        for (int kk = 0; kk < 16; kk++) {
            float4 a  = *(float4*)&Xs [kk][ty * 4];
            float4 b1 = *(float4*)&Bgs[kk][tx * 4];
            float4 b2 = *(float4*)&Bus[kk][tx * 4];
            float ar[4]  = {a.x,  a.y,  a.z,  a.w};
            float bgr[4] = {b1.x, b1.y, b1.z, b1.w};
            float bur[4] = {b2.x, b2.y, b2.z, b2.w};
            #pragma unroll
            for (int i = 0; i < 4; i++)
                #pragma unroll
                for (int j = 0; j < 4; j++) {
                    accg[i][j] += ar[i] * bgr[j];
                    accu[i][j] += ar[i] * bur[j];
                }
        }
        __syncthreads();
    }

    size_t hbase = (size_t)(rowbase + mbase) * INTR;
    #pragma unroll
    for (int i = 0; i < 4; i++) {
        int m = ty * 4 + i;
        if (mbase + m < rows) {
            float r[4];
            #pragma unroll
            for (int j = 0; j < 4; j++) {
                float g = accg[i][j];
                float s = g / (1.0f + __expf(-g));   // silu
                r[j] = s * accu[i][j];
            }
            float4 hv = make_float4(r[0], r[1], r[2], r[3]);
            *(float4*)(g_h + hbase + (size_t)m * INTR + n0 + tx * 4) = hv;
        }
    }
}

// ---------------- kernel 5: GEMM2  out += (h * Wd) * route_weight ----------------
// grid: (HID/64, ceil(T/64), 17), block 256, tile 64x64, BK=16
__global__ void gemm2_kernel(const float* __restrict__ Wd, const float* __restrict__ Sd,
                             float* __restrict__ out, int T) {
    int slot  = blockIdx.z;
    int rows  = (slot < NEXP) ? g_count[slot] : T;
    int mbase = blockIdx.y * 64;
    if (mbase >= rows) return;
    int n0 = blockIdx.x * 64;
    int rowbase = (slot < NEXP) ? g_off[slot] : ROWS_ROUTED;

    const float* Bw = (slot < NEXP) ? Wd + (size_t)slot * INTR * HID : Sd;

    __shared__ float As[16][64];
    __shared__ float Bs[16][64];

    int tid = threadIdx.x;
    int tx = tid & 15, ty = tid >> 4;
    int lm = tid >> 2, lq = tid & 3;
    int bk = tid >> 4, bn = tid & 15;

    bool avalid = (mbase + lm) < rows;
    size_t habase = (size_t)(rowbase + mbase) * INTR;

    float acc[4][4] = {};

    for (int k0 = 0; k0 < INTR; k0 += 16) {
        float4 av = make_float4(0.f, 0.f, 0.f, 0.f);
        if (avalid) av = *(const float4*)(g_h + habase + (size_t)lm * INTR + k0 + lq * 4);
        As[lq * 4 + 0][lm] = av.x;
        As[lq * 4 + 1][lm] = av.y;
        As[lq * 4 + 2][lm] = av.z;
        As[lq * 4 + 3][lm] = av.w;
        *(float4*)&Bs[bk][bn * 4] = *(const float4*)(Bw + (size_t)(k0 + bk) * HID + n0 + bn * 4);
        __syncthreads();
        #pragma unroll
        for (int kk = 0; kk < 16; kk++) {
            float4 a = *(float4*)&As[kk][ty * 4];
            float4 b = *(float4*)&Bs[kk][tx * 4];
            float ar[4] = {a.x, a.y, a.z, a.w};
            float br[4] = {b.x, b.y, b.z, b.w};
            #pragma unroll
            for (int i = 0; i < 4; i++)
                #pragma unroll
                for (int j = 0; j < 4; j++)
                    acc[i][j] += ar[i] * br[j];
        }
        __syncthreads();
    }

    #pragma unroll
    for (int i = 0; i < 4; i++) {
        int m = ty * 4 + i;
        int trow = mbase + m;
        if (trow < rows) {
            int   tok = (slot < NEXP) ? g_tok[slot * MAXT + trow] : trow;
            float w   = (slot < NEXP) ? g_wt [slot * MAXT + trow] : 1.0f;
            #pragma unroll
            for (int j = 0; j < 4; j++)
                atomicAdd(&out[(size_t)tok * HID + n0 + tx * 4 + j], acc[i][j] * w);
        }
    }
}

// ---------------- launcher ----------------
extern "C" void kernel_launch(void* const* d_in, const int* in_sizes, int n_in,
                              void* d_out, int out_size) {
    const float* x  = (const float*)d_in[0];
    const float* rw = (const float*)d_in[1];
    const float* Wg = (const float*)d_in[2];
    const float* Wu = (const float*)d_in[3];
    const float* Wd = (const float*)d_in[4];
    const float* Sg = (const float*)d_in[5];
    const float* Su = (const float*)d_in[6];
    const float* Sd = (const float*)d_in[7];
    float* out = (float*)d_out;

    int T = in_sizes[0] / HID;          // 2048
    int ntok = T * HID;

    zero_kernel<<<(ntok + 255) / 256, 256>>>(out, ntok);
    router_kernel<<<(T + 7) / 8, 256>>>(x, rw, T);
    finalize_kernel<<<1, 32>>>(out, T, ntok, (out_size > ntok) ? 1 : 0);

    dim3 g1(INTR / 64, (T + 63) / 64, NEXP + 1);
    gemm1_kernel<<<g1, 256>>>(x, Wg, Wu, Sg, Su, T);

    dim3 g2(HID / 64, (T + 63) / 64, NEXP + 1);
    gemm2_kernel<<<g2, 256>>>(Wd, Sd, out, T);
}

// round 7
// speedup vs baseline: 2.4321x; 2.4321x over previous
#include <cuda_runtime.h>
#include <cuda_bf16.h>
#include <math.h>
#include <stdint.h>

constexpr int HID=896, INTR=2560, NEXP=16, TOPK=4, MAXT=2048;
constexpr int ROWS_ROUTED=MAXT*TOPK, ROWS_TOTAL=ROWS_ROUTED+MAXT, NSLOT=NEXP+1;
constexpr size_t WSLOT=(size_t)INTR*HID;
constexpr size_t WSZ=(size_t)NSLOT*WSLOT;

// ---------------- scratch ----------------
__device__ int   g_count[NEXP];
__device__ int   g_off[NEXP];
__device__ float g_probsum[NEXP];
__device__ int   g_tok[NEXP*MAXT];
__device__ float g_wt [NEXP*MAXT];
__device__ __align__(16) __nv_bfloat16 g_xhi[(size_t)MAXT*HID];
__device__ __align__(16) __nv_bfloat16 g_xlo[(size_t)MAXT*HID];
__device__ __align__(16) __nv_bfloat16 g_WgThi[WSZ], g_WgTlo[WSZ];  // [slot][INTR][HID] K-major
__device__ __align__(16) __nv_bfloat16 g_WuThi[WSZ], g_WuTlo[WSZ];
__device__ __align__(16) __nv_bfloat16 g_WdThi[WSZ], g_WdTlo[WSZ];  // [slot][HID][INTR] K-major
__device__ __align__(16) __nv_bfloat16 g_hhi[(size_t)ROWS_TOTAL*INTR];
__device__ __align__(16) __nv_bfloat16 g_hlo[(size_t)ROWS_TOTAL*INTR];

// ---------------- helpers ----------------
__device__ __forceinline__ uint32_t smem_u32(const void* p){
    uint32_t a; asm("{ .reg .u64 t; cvta.to.shared.u64 t, %1; cvt.u32.u64 %0, t; }":"=r"(a):"l"(p)); return a;
}
__device__ __forceinline__ void cpa(uint32_t dst, const void* src){
    asm volatile("cp.async.cg.shared.global [%0], [%1], 16;"::"r"(dst),"l"(src));
}
#define CP_COMMIT() asm volatile("cp.async.commit_group;":::"memory")
#define CP_WAIT(n)  asm volatile("cp.async.wait_group %0;"::"n"(n):"memory")
__device__ __forceinline__ void ldm4(uint32_t* r, uint32_t a){
    asm volatile("ldmatrix.sync.aligned.m8n8.x4.shared.b16 {%0,%1,%2,%3}, [%4];"
      :"=r"(r[0]),"=r"(r[1]),"=r"(r[2]),"=r"(r[3]):"r"(a));
}
__device__ __forceinline__ void mma16816(float* d, const uint32_t* a, const uint32_t* b){
    asm volatile("mma.sync.aligned.m16n8k16.row.col.f32.bf16.bf16.f32 "
      "{%0,%1,%2,%3},{%4,%5,%6,%7},{%8,%9},{%0,%1,%2,%3};"
      :"+f"(d[0]),"+f"(d[1]),"+f"(d[2]),"+f"(d[3])
      :"r"(a[0]),"r"(a[1]),"r"(a[2]),"r"(a[3]),"r"(b[0]),"r"(b[1]));
}
__device__ __forceinline__ uint32_t swz(uint32_t off){ return off ^ ((off>>3)&0x70); }

// copy R rows x 64 bf16-cols into SW128-swizzled smem via cp.async
template<int R>
__device__ __forceinline__ void cp_tile(uint32_t dst, const __nv_bfloat16* __restrict__ src,
                                        size_t rs, int tid){
    #pragma unroll
    for(int p=0;p<R*8/256;p++){
        int idx=tid+p*256, r=idx>>3, q=idx&7;
        cpa(dst+swz((uint32_t)(r*128+q*16)), src+(size_t)r*rs+q*8);
    }
}
// gathered x tile (hi+lo), 128 rows x 64 cols
__device__ __forceinline__ void cp_tileA(uint32_t dh, uint32_t dl,
        const int* __restrict__ stok, int k0, int tid){
    #pragma unroll
    for(int p=0;p<4;p++){
        int idx=tid+p*256, r=idx>>3, q=idx&7;
        size_t sb=(size_t)stok[r]*HID+k0+q*8;
        uint32_t sw=swz((uint32_t)(r*128+q*16));
        cpa(dh+sw, g_xhi+sb);
        cpa(dl+sw, g_xlo+sb);
    }
}

// ---------------- small kernels ----------------
__global__ void zero_kernel(float* __restrict__ out, int n){
    int i=blockIdx.x*blockDim.x+threadIdx.x;
    if(i<n) out[i]=0.0f;
    if(blockIdx.x==0&&threadIdx.x<NEXP){ g_count[threadIdx.x]=0; g_probsum[threadIdx.x]=0.0f; }
}
__global__ void split_x_kernel(const float* __restrict__ x, int n){
    int i=blockIdx.x*blockDim.x+threadIdx.x;
    if(i>=n) return;
    float v=x[i];
    __nv_bfloat16 h=__float2bfloat16(v);
    g_xhi[i]=h; g_xlo[i]=__float2bfloat16(v-__bfloat162float(h));
}
__global__ void transpose_split_kernel(const float* __restrict__ src,
                                       int dstsel, int slot0, int K, int N){
    __nv_bfloat16 *dhi,*dlo;
    if(dstsel==0){dhi=g_WgThi;dlo=g_WgTlo;} else if(dstsel==1){dhi=g_WuThi;dlo=g_WuTlo;}
    else {dhi=g_WdThi;dlo=g_WdTlo;}
    __shared__ float t[32][33];
    const float* s=src+(size_t)blockIdx.z*K*N;
    size_t db=(size_t)(slot0+blockIdx.z)*WSLOT;
    int n0=blockIdx.x*32, k0=blockIdx.y*32, tx=threadIdx.x, ty=threadIdx.y;
    #pragma unroll
    for(int i=0;i<32;i+=8) t[ty+i][tx]=s[(size_t)(k0+ty+i)*N+n0+tx];
    __syncthreads();
    #pragma unroll
    for(int i=0;i<32;i+=8){
        float v=t[tx][ty+i];
        __nv_bfloat16 h=__float2bfloat16(v);
        size_t o=db+(size_t)(n0+ty+i)*K+(k0+tx);
        dhi[o]=h; dlo[o]=__float2bfloat16(v-__bfloat162float(h));
    }
}
__global__ void router_kernel(const float* __restrict__ x, const float* __restrict__ rw, int T){
    int warp=(blockIdx.x*blockDim.x+threadIdx.x)>>5, lane=threadIdx.x&31;
    if(warp>=T) return;
    const float* xr=x+(size_t)warp*HID;
    float logit=-1e30f;
    if(lane<NEXP){ float s=0.f; for(int d=0;d<HID;d++) s+=xr[d]*rw[d*NEXP+lane]; logit=s; }
    float m=logit;
    #pragma unroll
    for(int o=8;o>=1;o>>=1) m=fmaxf(m,__shfl_xor_sync(0xffffffffu,m,o));
    float p=(lane<NEXP)?__expf(logit-m):0.f;
    float sum=p;
    #pragma unroll
    for(int o=8;o>=1;o>>=1) sum+=__shfl_xor_sync(0xffffffffu,sum,o);
    p/=sum;
    if(lane<NEXP) atomicAdd(&g_probsum[lane],p);
    float pv[NEXP];
    #pragma unroll
    for(int e=0;e<NEXP;e++) pv[e]=__shfl_sync(0xffffffffu,p,e);
    if(lane==0){
        bool used[NEXP];
        #pragma unroll
        for(int e=0;e<NEXP;e++) used[e]=false;
        int idx[TOPK]; float val[TOPK]; float s4=0.f;
        #pragma unroll
        for(int k=0;k<TOPK;k++){
            int bi=-1; float bv=-1.f;
            #pragma unroll
            for(int e=0;e<NEXP;e++) if(!used[e]&&pv[e]>bv){bv=pv[e];bi=e;}
            used[bi]=true; idx[k]=bi; val[k]=bv; s4+=bv;
        }
        float inv=1.f/(s4+1e-8f);
        #pragma unroll
        for(int k=0;k<TOPK;k++){
            int e=idx[k], pos=atomicAdd(&g_count[e],1);
            g_tok[e*MAXT+pos]=warp; g_wt[e*MAXT+pos]=val[k]*inv;
        }
    }
}
__global__ void finalize_kernel(float* __restrict__ out, int T, int ofs, int has_loss){
    if(threadIdx.x==0){
        int s=0; float loss=0.f;
        for(int e=0;e<NEXP;e++){
            g_off[e]=s; s+=g_count[e];
            loss+=((float)g_count[e]/(float)T)*(g_probsum[e]/(float)T);
        }
        if(has_loss) out[ofs]=loss*(float)NEXP;
    }
}

// ---------------- GEMM1: h = silu(x*Wg)*(x*Wu) ----------------
// block tile: M=128, Ng=64 (warps 0-3), Nu=64 (warps 4-7); warp tile 64x32; K-chunk 64
constexpr int B1_AH=0, B1_AL=16384, B1_GH=32768, B1_GL=40960, B1_UH=49152, B1_UL=57344;
constexpr int BUF1=65536;
constexpr int SMEM1=2*BUF1+1024;

__global__ void __launch_bounds__(256,1) gemm1_mma(int T){
    int slot=blockIdx.z;
    int rows=(slot<NEXP)?g_count[slot]:T;
    int mbase=blockIdx.y*128;
    if(mbase>=rows) return;
    int n0=blockIdx.x*64;
    int rowbase=(slot<NEXP)?g_off[slot]:ROWS_ROUTED;
    extern __shared__ __align__(1024) char smem[];
    uint32_t smb=smem_u32(smem);
    int tid=threadIdx.x, wid=tid>>5, lane=tid&31;
    int* stok=(int*)(smem+2*BUF1);
    if(tid<128){
        int m=mbase+tid, mm=(m<rows)?m:rows-1;
        stok[tid]=(slot<NEXP)?g_tok[slot*MAXT+mm]:mm;
    }
    __syncthreads();

    size_t wb=(size_t)slot*WSLOT+(size_t)n0*HID;
    bool is_u = wid>=4;
    int w4=wid&3, mo=(w4&1)*64, no=(w4>>1)*32;
    uint32_t bHoff = is_u? (uint32_t)B1_UH : (uint32_t)B1_GH;
    uint32_t bLoff = is_u? (uint32_t)B1_UL : (uint32_t)B1_GL;

    // per-lane ldmatrix base offsets (pre-swizzle)
    uint32_t aRow = (uint32_t)(mo + (lane&15));
    uint32_t aKb  = (uint32_t)((lane>>4)*16);
    uint32_t bRow = (uint32_t)(no + (lane&7) + ((lane>>4)&1)*8);
    uint32_t bKb  = (uint32_t)(((lane>>3)&1)*16);

    float acc[4][4][4];
    #pragma unroll
    for(int i=0;i<4;i++)
        #pragma unroll
        for(int j=0;j<4;j++)
            #pragma unroll
            for(int q=0;q<4;q++) acc[i][j][q]=0.f;

    auto load_chunk=[&](int c){
        uint32_t base=smb+(uint32_t)(c&1)*BUF1;
        int k0=c*64;
        cp_tileA(base+B1_AH, base+B1_AL, stok, k0, tid);
        size_t wk=wb+k0;
        cp_tile<64>(base+B1_GH, g_WgThi+wk, HID, tid);
        cp_tile<64>(base+B1_GL, g_WgTlo+wk, HID, tid);
        cp_tile<64>(base+B1_UH, g_WuThi+wk, HID, tid);
        cp_tile<64>(base+B1_UL, g_WuTlo+wk, HID, tid);
    };

    const int NC=HID/64;  // 14
    load_chunk(0); CP_COMMIT();
    for(int c=0;c<NC;c++){
        if(c+1<NC){ load_chunk(c+1); CP_COMMIT(); CP_WAIT(1); } else { CP_WAIT(0); }
        __syncthreads();
        uint32_t base=smb+(uint32_t)(c&1)*BUF1;
        #pragma unroll
        for(int ks=0;ks<4;ks++){
            uint32_t aH[4][4], aL[4][4], bH[2][4], bL[2][4];
            #pragma unroll
            for(int mi=0;mi<4;mi++){
                uint32_t off=(aRow+mi*16)*128 + ks*32 + aKb;
                ldm4(aH[mi], base+B1_AH+swz(off));
                ldm4(aL[mi], base+B1_AL+swz(off));
            }
            #pragma unroll
            for(int j=0;j<2;j++){
                uint32_t off=(bRow+j*16)*128 + ks*32 + bKb;
                ldm4(bH[j], base+bHoff+swz(off));
                ldm4(bL[j], base+bLoff+swz(off));
            }
            #pragma unroll
            for(int mi=0;mi<4;mi++)
                #pragma unroll
                for(int nj=0;nj<4;nj++){
                    const uint32_t* bh=&bH[nj>>1][(nj&1)*2];
                    const uint32_t* bl=&bL[nj>>1][(nj&1)*2];
                    mma16816(acc[mi][nj], aH[mi], bh);
                    mma16816(acc[mi][nj], aH[mi], bl);
                    mma16816(acc[mi][nj], aL[mi], bh);
                }
        }
        __syncthreads();
    }

    // epilogue: exchange g/u through smem (reuse buffer 0), silu, store bf16 hi/lo
    float* gs=(float*)smem;             // [128][64]
    float* us=(float*)(smem+32768);     // [128][64]
    float* dst = is_u ? us : gs;
    #pragma unroll
    for(int mi=0;mi<4;mi++)
        #pragma unroll
        for(int nj=0;nj<4;nj++){
            int r=mo+mi*16+(lane>>2), cl=no+nj*8+(lane&3)*2;
            dst[r*64+cl]    =acc[mi][nj][0];
            dst[r*64+cl+1]  =acc[mi][nj][1];
            dst[(r+8)*64+cl]  =acc[mi][nj][2];
            dst[(r+8)*64+cl+1]=acc[mi][nj][3];
        }
    __syncthreads();
    #pragma unroll
    for(int p=0;p<32;p++){
        int idx=p*256+tid, m=idx>>6, n=idx&63;
        if(mbase+m<rows){
            float g=gs[idx], u=us[idx];
            float v=g/(1.f+__expf(-g))*u;
            float h=__bfloat162float(__float2bfloat16(v));
            size_t o=(size_t)(rowbase+mbase+m)*INTR + n0 + n;
            g_hhi[o]=__float2bfloat16(h);
            g_hlo[o]=__float2bfloat16(v-h);
        }
    }
}

// ---------------- GEMM2: out += (h*Wd)*weight ----------------
// block tile: M=128, N=128; warp tile 64x32; K-chunk 64
constexpr int B2_AH=0, B2_AL=16384, B2_BH=32768, B2_BL=49152;
constexpr int BUF2=65536;
constexpr int SMEM2=2*BUF2+1024;

__global__ void __launch_bounds__(256,1) gemm2_mma(float* __restrict__ out, int T){
    int slot=blockIdx.z;
    int rows=(slot<NEXP)?g_count[slot]:T;
    int mbase=blockIdx.y*128;
    if(mbase>=rows) return;
    int n0=blockIdx.x*128;
    int rowbase=(slot<NEXP)?g_off[slot]:ROWS_ROUTED;
    extern __shared__ __align__(1024) char smem[];
    uint32_t smb=smem_u32(smem);
    int tid=threadIdx.x, wid=tid>>5, lane=tid&31;

    const __nv_bfloat16* Ah=g_hhi+(size_t)(rowbase+mbase)*INTR;
    const __nv_bfloat16* Al=g_hlo+(size_t)(rowbase+mbase)*INTR;
    size_t wb=(size_t)slot*WSLOT+(size_t)n0*INTR;

    int mo=(wid&1)*64, no=(wid>>1)*32;
    uint32_t aRow=(uint32_t)(mo+(lane&15)), aKb=(uint32_t)((lane>>4)*16);
    uint32_t bRow=(uint32_t)(no+(lane&7)+((lane>>4)&1)*8), bKb=(uint32_t)(((lane>>3)&1)*16);

    float acc[4][4][4];
    #pragma unroll
    for(int i=0;i<4;i++)
        #pragma unroll
        for(int j=0;j<4;j++)
            #pragma unroll
            for(int q=0;q<4;q++) acc[i][j][q]=0.f;

    auto load_chunk=[&](int c){
        uint32_t base=smb+(uint32_t)(c&1)*BUF2;
        int k0=c*64;
        cp_tile<128>(base+B2_AH, Ah+k0, INTR, tid);
        cp_tile<128>(base+B2_AL, Al+k0, INTR, tid);
        cp_tile<128>(base+B2_BH, g_WdThi+wb+k0, INTR, tid);
        cp_tile<128>(base+B2_BL, g_WdTlo+wb+k0, INTR, tid);
    };

    const int NC=INTR/64;  // 40
    load_chunk(0); CP_COMMIT();
    for(int c=0;c<NC;c++){
        if(c+1<NC){ load_chunk(c+1); CP_COMMIT(); CP_WAIT(1); } else { CP_WAIT(0); }
        __syncthreads();
        uint32_t base=smb+(uint32_t)(c&1)*BUF2;
        #pragma unroll
        for(int ks=0;ks<4;ks++){
            uint32_t aH[4][4], aL[4][4], bH[2][4], bL[2][4];
            #pragma unroll
            for(int mi=0;mi<4;mi++){
                uint32_t off=(aRow+mi*16)*128 + ks*32 + aKb;
                ldm4(aH[mi], base+B2_AH+swz(off));
                ldm4(aL[mi], base+B2_AL+swz(off));
            }
            #pragma unroll
            for(int j=0;j<2;j++){
                uint32_t off=(bRow+j*16)*128 + ks*32 + bKb;
                ldm4(bH[j], base+B2_BH+swz(off));
                ldm4(bL[j], base+B2_BL+swz(off));
            }
            #pragma unroll
            for(int mi=0;mi<4;mi++)
                #pragma unroll
                for(int nj=0;nj<4;nj++){
                    const uint32_t* bh=&bH[nj>>1][(nj&1)*2];
                    const uint32_t* bl=&bL[nj>>1][(nj&1)*2];
                    mma16816(acc[mi][nj], aH[mi], bh);
                    mma16816(acc[mi][nj], aH[mi], bl);
                    mma16816(acc[mi][nj], aL[mi], bh);
                }
        }
        __syncthreads();
    }

    // epilogue: weighted atomic scatter
    #pragma unroll
    for(int mi=0;mi<4;mi++){
        #pragma unroll
        for(int half=0;half<2;half++){
            int r=mo+mi*16+(lane>>2)+half*8;
            int trow=mbase+r;
            if(trow<rows){
                int tok=(slot<NEXP)?g_tok[slot*MAXT+trow]:trow;
                float w=(slot<NEXP)?g_wt[slot*MAXT+trow]:1.f;
                float* op=out+(size_t)tok*HID+n0;
                #pragma unroll
                for(int nj=0;nj<4;nj++){
                    int cl=no+nj*8+(lane&3)*2;
                    atomicAdd(&op[cl],   acc[mi][nj][half*2]  *w);
                    atomicAdd(&op[cl+1], acc[mi][nj][half*2+1]*w);
                }
            }
        }
    }
}

// ---------------- launcher ----------------
extern "C" void kernel_launch(void* const* d_in, const int* in_sizes, int n_in,
                              void* d_out, int out_size){
    const float* x =(const float*)d_in[0];
    const float* rw=(const float*)d_in[1];
    const float* Wg=(const float*)d_in[2];
    const float* Wu=(const float*)d_in[3];
    const float* Wd=(const float*)d_in[4];
    const float* Sg=(const float*)d_in[5];
    const float* Su=(const float*)d_in[6];
    const float* Sd=(const float*)d_in[7];
    float* out=(float*)d_out;
    int T=in_sizes[0]/HID, ntok=T*HID;

    cudaFuncSetAttribute(gemm1_mma, cudaFuncAttributeMaxDynamicSharedMemorySize, SMEM1);
    cudaFuncSetAttribute(gemm2_mma, cudaFuncAttributeMaxDynamicSharedMemorySize, SMEM2);

    zero_kernel<<<(ntok+255)/256,256>>>(out,ntok);
    split_x_kernel<<<(ntok+255)/256,256>>>(x,ntok);
    dim3 tb(32,8);
    transpose_split_kernel<<<dim3(INTR/32,HID/32,NEXP),tb>>>(Wg,0,0,HID,INTR);
    transpose_split_kernel<<<dim3(INTR/32,HID/32,1),   tb>>>(Sg,0,NEXP,HID,INTR);
    transpose_split_kernel<<<dim3(INTR/32,HID/32,NEXP),tb>>>(Wu,1,0,HID,INTR);
    transpose_split_kernel<<<dim3(INTR/32,HID/32,1),   tb>>>(Su,1,NEXP,HID,INTR);
    transpose_split_kernel<<<dim3(HID/32,INTR/32,NEXP),tb>>>(Wd,2,0,INTR,HID);
    transpose_split_kernel<<<dim3(HID/32,INTR/32,1),   tb>>>(Sd,2,NEXP,INTR,HID);
    router_kernel<<<(T+7)/8,256>>>(x,rw,T);
    finalize_kernel<<<1,32>>>(out,T,ntok,(out_size>ntok)?1:0);

    gemm1_mma<<<dim3(INTR/64, MAXT/128, NSLOT),256,SMEM1>>>(T);
    gemm2_mma<<<dim3(HID/128, MAXT/128, NSLOT),256,SMEM2>>>(out,T);
}